// round 7
// baseline (speedup 1.0000x reference)
#include <cuda_runtime.h>
#include <cuda_bf16.h>
#include <cstdint>

#define D 64
#define MAX_NODES 100000

// scratch (no cudaMalloc allowed): bf16 neighbor sums + bf16 copy of emb.
__device__ __align__(16) __nv_bfloat16 g_nbr[(size_t)MAX_NODES * D];
__device__ __align__(16) __nv_bfloat16 g_embh[(size_t)MAX_NODES * D];

static __device__ __forceinline__ uint32_t pack_bf2(float a, float b) {
    uint32_t r;
    asm("cvt.rn.bf16x2.f32 %0, %1, %2;" : "=r"(r) : "f"(b), "f"(a));  // lo=a, hi=b
    return r;
}

// ---------------------------------------------------------------------------
// Kernel 1: prep — convert emb fp32 -> bf16 scratch, zero g_nbr, zero d_out.
// ---------------------------------------------------------------------------
__global__ __launch_bounds__(256) void prep_kernel(const float* __restrict__ emb,
                                                   float* __restrict__ out,
                                                   int n_grp) {
    int i = blockIdx.x * blockDim.x + threadIdx.x;
    if (i < n_grp) {
        float4 v = __ldg(reinterpret_cast<const float4*>(emb) + i);
        uint2 pk;
        pk.x = pack_bf2(v.x, v.y);
        pk.y = pack_bf2(v.z, v.w);
        reinterpret_cast<uint2*>(g_embh)[i] = pk;
        reinterpret_cast<uint2*>(g_nbr)[i] = make_uint2(0u, 0u);
    }
    if (i < D / 4) reinterpret_cast<float4*>(out)[i] = make_float4(0.f, 0.f, 0.f, 0.f);
}

// ---------------------------------------------------------------------------
// Kernel 2: edge scatter  nbr[dst] += emb_bf16[src]   (8 lanes/edge, RED.128)
// ---------------------------------------------------------------------------
#define SCAT_BLOCKS 4736

__global__ __launch_bounds__(256) void scatter_kernel(
    const int* __restrict__ src,
    const int* __restrict__ dst,
    int n_items) {
    int stride = gridDim.x * blockDim.x;
    for (int i = blockIdx.x * blockDim.x + threadIdx.x; i < n_items; i += stride) {
        int e = i >> 3;
        int c = i & 7;
        int s = __ldg(src + e);
        int d = __ldg(dst + e);
        uint4 v = *(reinterpret_cast<const uint4*>(g_embh) + (size_t)s * 8 + c);
        __nv_bfloat16* p = g_nbr + (size_t)d * D + c * 8;
        asm volatile("red.global.add.noftz.v4.bf16x2 [%0], {%1,%2,%3,%4};"
                     :: "l"(p), "r"(v.x), "r"(v.y), "r"(v.z), "r"(v.w)
                     : "memory");
    }
}

// ---------------------------------------------------------------------------
// Kernel 3: fused MLP + relu + graph-sum, paired-GEMM f32x2.
//   out += sum_v relu(feat[v] @ W1^T + b1 + nbr[v] @ W2^T + b2)
// The two GEMMs are packed against each other:
//   cS[v][k] = u64 pair (feat[v][k], nbr[v][k])
//   Wp[k][o] = u64 pair (W1[o][k],  W2[o][k])
//   one fma.rn.f32x2 -> lo accumulates feat@W1, hi accumulates nbr@W2.
// R4 blocking kept: 256 thr = 16 node-slots x 16 out-groups; thread = 4 nodes
// x 4 outputs = 16 independent packed acc chains. 444 CTAs (3/SM).
// ---------------------------------------------------------------------------
#define FMA2(acc, a, b) \
    asm("fma.rn.f32x2 %0, %1, %2, %0;" : "+l"(acc) : "l"(a), "l"(b))

#define MLP_BLOCKS 444
#define MLP_SMEM   65536   // cS 32KB + Wp 32KB (dynamic)

__global__ __launch_bounds__(256) void mlp_kernel(
    const float* __restrict__ feat,
    const float* __restrict__ W1,
    const float* __restrict__ b1,
    const float* __restrict__ W2,
    const float* __restrict__ b2,
    float* __restrict__ out,
    int n_nodes) {

    extern __shared__ uint64_t sm64[];
    uint64_t* cS = sm64;            // [64 nodes][64 k] pairs, 32KB
    uint64_t* Wp = sm64 + 4096;     // [64 k][64 o] pairs,   32KB
    __shared__ float bc[D];
    __shared__ float redbuf[16][D];

    const int t = threadIdx.x;

    // build weight-pair table: Wp[k*64+o] = (W1[o][k], W2[o][k])
    // i-consecutive => k-consecutive: coalesced global reads.
    for (int i = t; i < D * D; i += 256) {
        int k = i & 63, o = i >> 6;
        uint64_t w1 = (uint64_t)__float_as_uint(__ldg(W1 + o * D + k));
        uint64_t w2 = (uint64_t)__float_as_uint(__ldg(W2 + o * D + k));
        Wp[k * D + o] = w1 | (w2 << 32);
    }
    if (t < D) bc[t] = __ldg(b1 + t) + __ldg(b2 + t);

    const int og   = t & 15;      // outputs og*4 .. og*4+3
    const int slot = t >> 4;      // nodes  slot*4 .. slot*4+3

    float4 gsum = make_float4(0.f, 0.f, 0.f, 0.f);
    const int n_tiles = (n_nodes + 63) >> 6;

    for (int tile = blockIdx.x; tile < n_tiles; tile += gridDim.x) {
        const int base = tile << 6;
        __syncthreads();   // protect prev iter reads (and Wp build, iter 0)

        // stage pairs: 64 rows x 32 uint4 (each uint4 = 2 k-pairs)
        #pragma unroll
        for (int j = 0; j < 8; j++) {
            int idx = t + j * 256;          // 0..2047
            int row = idx >> 5;
            int kp  = idx & 31;             // k-pair: ks 2kp, 2kp+1
            int v = base + row;
            uint4 st = make_uint4(0u, 0u, 0u, 0u);
            if (v < n_nodes) {
                float2 f = __ldg(reinterpret_cast<const float2*>(feat + (size_t)v * D) + kp);
                uint32_t nb = *(reinterpret_cast<const uint32_t*>(g_nbr + (size_t)v * D) + kp);
                st.x = __float_as_uint(f.x);
                st.y = nb << 16;             // bf16 -> f32 exact
                st.z = __float_as_uint(f.y);
                st.w = nb & 0xffff0000u;
            }
            reinterpret_cast<uint4*>(cS)[idx] = st;
        }
        __syncthreads();

        uint64_t acc[4][4];   // [node][out], packed (featW1, nbrW2)
        #pragma unroll
        for (int n = 0; n < 4; n++)
            #pragma unroll
            for (int o = 0; o < 4; o++) acc[n][o] = 0ull;

        const ulonglong2* c2 = reinterpret_cast<const ulonglong2*>(cS);
        const ulonglong2* w2p = reinterpret_cast<const ulonglong2*>(Wp);

        #pragma unroll 4
        for (int k4 = 0; k4 < 16; k4++) {
            uint64_t d[4][4];
            #pragma unroll
            for (int n = 0; n < 4; n++) {
                ulonglong2 a = c2[(slot * 4 + n) * 32 + k4 * 2];
                ulonglong2 b = c2[(slot * 4 + n) * 32 + k4 * 2 + 1];
                d[n][0] = a.x; d[n][1] = a.y; d[n][2] = b.x; d[n][3] = b.y;
            }
            #pragma unroll
            for (int kk = 0; kk < 4; kk++) {
                int k = k4 * 4 + kk;
                ulonglong2 wa = w2p[k * 32 + og * 2];
                ulonglong2 wb = w2p[k * 32 + og * 2 + 1];
                uint64_t w0 = wa.x, w1 = wa.y, w2v = wb.x, w3 = wb.y;
                #pragma unroll
                for (int n = 0; n < 4; n++) {
                    FMA2(acc[n][0], d[n][kk], w0);
                    FMA2(acc[n][1], d[n][kk], w1);
                    FMA2(acc[n][2], d[n][kk], w2v);
                    FMA2(acc[n][3], d[n][kk], w3);
                }
            }
        }

        // bias + relu + accumulate per-thread graph sum (guarded per node)
        #pragma unroll
        for (int n = 0; n < 4; n++) {
            if (base + slot * 4 + n < n_nodes) {
                float v0 = __uint_as_float((uint32_t)acc[n][0]) + __uint_as_float((uint32_t)(acc[n][0] >> 32)) + bc[og * 4 + 0];
                float v1 = __uint_as_float((uint32_t)acc[n][1]) + __uint_as_float((uint32_t)(acc[n][1] >> 32)) + bc[og * 4 + 1];
                float v2 = __uint_as_float((uint32_t)acc[n][2]) + __uint_as_float((uint32_t)(acc[n][2] >> 32)) + bc[og * 4 + 2];
                float v3 = __uint_as_float((uint32_t)acc[n][3]) + __uint_as_float((uint32_t)(acc[n][3] >> 32)) + bc[og * 4 + 3];
                gsum.x += fmaxf(v0, 0.f);
                gsum.y += fmaxf(v1, 0.f);
                gsum.z += fmaxf(v2, 0.f);
                gsum.w += fmaxf(v3, 0.f);
            }
        }
    }

    // block reduction: 16 slots -> 1, then atomic into d_out
    __syncthreads();
    reinterpret_cast<float4*>(&redbuf[slot][0])[og] = gsum;
    __syncthreads();
    if (t < D) {
        float s = 0.f;
        #pragma unroll
        for (int r = 0; r < 16; r++) s += redbuf[r][t];
        atomicAdd(out + t, s);
    }
}

// ---------------------------------------------------------------------------
// launch — inputs (metadata order): feat, emb, W1, b1, W2, b2, edge_src, edge_dst
// ---------------------------------------------------------------------------
extern "C" void kernel_launch(void* const* d_in, const int* in_sizes, int n_in,
                              void* d_out, int out_size) {
    (void)n_in; (void)out_size;
    const float* feat = (const float*)d_in[0];
    const float* emb  = (const float*)d_in[1];
    const float* W1   = (const float*)d_in[2];
    const float* b1   = (const float*)d_in[3];
    const float* W2   = (const float*)d_in[4];
    const float* b2   = (const float*)d_in[5];
    const int* esrc   = (const int*)d_in[6];
    const int* edst   = (const int*)d_in[7];
    float* out        = (float*)d_out;

    const int n_nodes = in_sizes[0] / D;
    const int n_edges = in_sizes[6];

    // 1) prep: emb->bf16, zero scratch + out
    {
        int n_grp = n_nodes * (D / 4);
        int blocks = (n_grp + 255) / 256;
        prep_kernel<<<blocks, 256>>>(emb, out, n_grp);
    }
    // 2) scatter (bf16 RED.128)
    {
        int n_items = n_edges * 8;
        scatter_kernel<<<SCAT_BLOCKS, 256>>>(esrc, edst, n_items);
    }
    // 3) MLP + relu + graph reduce (paired-GEMM f32x2)
    cudaFuncSetAttribute(mlp_kernel, cudaFuncAttributeMaxDynamicSharedMemorySize, MLP_SMEM);
    mlp_kernel<<<MLP_BLOCKS, 256, MLP_SMEM>>>(feat, W1, b1, W2, b2, out, n_nodes);
}

// round 8
// speedup vs baseline: 1.6183x; 1.6183x over previous
#include <cuda_runtime.h>
#include <cuda_bf16.h>
#include <cstdint>

#define D 64
#define MAX_NODES 100000

// scratch (no cudaMalloc allowed)
__device__ __align__(16) __nv_bfloat16 g_nbr[(size_t)MAX_NODES * D];   // bf16 neighbor sums
__device__ __align__(16) __nv_bfloat16 g_embh[(size_t)MAX_NODES * D];  // bf16 emb copy
__device__ __align__(16) float g_z[(size_t)MAX_NODES * D];             // feat@W1^T + b1 + b2

static __device__ __forceinline__ uint32_t pack_bf2(float a, float b) {
    uint32_t r;
    asm("cvt.rn.bf16x2.f32 %0, %1, %2;" : "=r"(r) : "f"(b), "f"(a));  // lo=a, hi=b
    return r;
}

// ---------------------------------------------------------------------------
// Kernel 1: prep — convert emb fp32 -> bf16 scratch, zero g_nbr, zero d_out.
// ---------------------------------------------------------------------------
__global__ __launch_bounds__(256) void prep_kernel(const float* __restrict__ emb,
                                                   float* __restrict__ out,
                                                   int n_grp) {
    int i = blockIdx.x * blockDim.x + threadIdx.x;
    if (i < n_grp) {
        float4 v = __ldg(reinterpret_cast<const float4*>(emb) + i);
        uint2 pk;
        pk.x = pack_bf2(v.x, v.y);
        pk.y = pack_bf2(v.z, v.w);
        reinterpret_cast<uint2*>(g_embh)[i] = pk;
        reinterpret_cast<uint2*>(g_nbr)[i] = make_uint2(0u, 0u);
    }
    if (i < D / 4) reinterpret_cast<float4*>(out)[i] = make_float4(0.f, 0.f, 0.f, 0.f);
}

// ---------------------------------------------------------------------------
// Kernel 2 (FUSED): block-specialized.
//   blocks [0, NG)            : phase-A GEMM  Z = feat @ W1^T + (b1+b2)
//   blocks [NG, NG+SCAT_BLK)  : edge scatter  nbr[dst] += emb_bf16[src]
// The GEMM is FMA-bound, the scatter is L2/atomic-bound -> they overlap.
// ---------------------------------------------------------------------------
#define NG         148
#define SCAT_BLK   4736

__global__ __launch_bounds__(256) void fused_kernel(
    const float* __restrict__ feat,
    const float* __restrict__ W1,
    const float* __restrict__ b1,
    const float* __restrict__ b2,
    const int* __restrict__ src,
    const int* __restrict__ dst,
    int n_items, int n_nodes) {

    __shared__ float W1t[D * D];     // [k][o], 16KB
    __shared__ float fS[64][D];      // [node][k], 16KB

    const int t = threadIdx.x;

    if (blockIdx.x >= NG) {
        // ------- scatter path (no smem, no syncs) -------
        int stride = SCAT_BLK * 256;
        for (int i = (blockIdx.x - NG) * 256 + t; i < n_items; i += stride) {
            int e = i >> 3;
            int c = i & 7;
            int s = __ldg(src + e);
            int d = __ldg(dst + e);
            uint4 v = *(reinterpret_cast<const uint4*>(g_embh) + (size_t)s * 8 + c);
            __nv_bfloat16* p = g_nbr + (size_t)d * D + c * 8;
            asm volatile("red.global.add.noftz.v4.bf16x2 [%0], {%1,%2,%3,%4};"
                         :: "l"(p), "r"(v.x), "r"(v.y), "r"(v.z), "r"(v.w)
                         : "memory");
        }
        return;
    }

    // ------- phase-A GEMM path -------
    for (int i = t; i < D * D; i += 256) {
        int o = i >> 6, k = i & 63;
        W1t[k * D + o] = __ldg(W1 + i);
    }

    const int og   = t & 15;      // outputs og*4 .. og*4+3
    const int slot = t >> 4;      // nodes  slot*4 .. slot*4+3

    float4 bcv;
    {
        float4 v1 = __ldg(reinterpret_cast<const float4*>(b1) + og);
        float4 v2 = __ldg(reinterpret_cast<const float4*>(b2) + og);
        bcv = make_float4(v1.x + v2.x, v1.y + v2.y, v1.z + v2.z, v1.w + v2.w);
    }

    const int n_tiles = (n_nodes + 63) >> 6;
    for (int tile = blockIdx.x; tile < n_tiles; tile += NG) {
        const int base = tile << 6;
        __syncthreads();
        #pragma unroll
        for (int j = 0; j < 4; j++) {
            int idx = t + j * 256;
            int row = idx >> 4;
            int v = base + row;
            float4 val = (v < n_nodes)
                ? __ldg(reinterpret_cast<const float4*>(feat) + (size_t)v * 16 + (idx & 15))
                : make_float4(0.f, 0.f, 0.f, 0.f);
            reinterpret_cast<float4*>(&fS[0][0])[idx] = val;
        }
        __syncthreads();

        float4 acc[4];
        #pragma unroll
        for (int n = 0; n < 4; n++) acc[n] = bcv;

        #pragma unroll 4
        for (int k4 = 0; k4 < 16; k4++) {
            float fa[4][4];
            #pragma unroll
            for (int n = 0; n < 4; n++) {
                float4 fv = reinterpret_cast<const float4*>(&fS[slot * 4 + n][0])[k4];
                fa[n][0] = fv.x; fa[n][1] = fv.y; fa[n][2] = fv.z; fa[n][3] = fv.w;
            }
            #pragma unroll
            for (int kk = 0; kk < 4; kk++) {
                int k = k4 * 4 + kk;
                float4 w1 = reinterpret_cast<const float4*>(W1t + k * D)[og];
                #pragma unroll
                for (int n = 0; n < 4; n++) {
                    acc[n].x += fa[n][kk] * w1.x;
                    acc[n].y += fa[n][kk] * w1.y;
                    acc[n].z += fa[n][kk] * w1.z;
                    acc[n].w += fa[n][kk] * w1.w;
                }
            }
        }

        #pragma unroll
        for (int n = 0; n < 4; n++) {
            int v = base + slot * 4 + n;
            if (v < n_nodes) {
                reinterpret_cast<float4*>(g_z + (size_t)v * D)[og] = acc[n];
            }
        }
    }
}

// ---------------------------------------------------------------------------
// Kernel 3: phase-B  out += sum_v relu(Z[v] + nbr[v] @ W2^T)
// R4 blocking: 256 thr = 16 node-slots x 16 out-groups, 4x4 register tile.
// ---------------------------------------------------------------------------
#define MLPB_BLOCKS 444

__global__ __launch_bounds__(256) void mlpb_kernel(
    const float* __restrict__ W2,
    float* __restrict__ out,
    int n_nodes) {

    __shared__ float W2t[D * D];     // [k][o]
    __shared__ float nS[64][D];
    __shared__ float redbuf[16][D];

    const int t = threadIdx.x;

    for (int i = t; i < D * D; i += 256) {
        int o = i >> 6, k = i & 63;
        W2t[k * D + o] = __ldg(W2 + i);
    }

    const int og   = t & 15;
    const int slot = t >> 4;

    float4 gsum = make_float4(0.f, 0.f, 0.f, 0.f);
    const int n_tiles = (n_nodes + 63) >> 6;

    for (int tile = blockIdx.x; tile < n_tiles; tile += gridDim.x) {
        const int base = tile << 6;
        __syncthreads();
        // stage nbr (bf16 -> fp32 exact)
        #pragma unroll
        for (int j = 0; j < 2; j++) {
            int p = t + j * 256;
            int row = p >> 3;
            int v = base + row;
            uint4 u = (v < n_nodes)
                ? *(reinterpret_cast<const uint4*>(g_nbr) + (size_t)v * 8 + (p & 7))
                : make_uint4(0u, 0u, 0u, 0u);
            float4 lo, hi;
            lo.x = __uint_as_float(u.x << 16); lo.y = __uint_as_float(u.x & 0xffff0000u);
            lo.z = __uint_as_float(u.y << 16); lo.w = __uint_as_float(u.y & 0xffff0000u);
            hi.x = __uint_as_float(u.z << 16); hi.y = __uint_as_float(u.z & 0xffff0000u);
            hi.z = __uint_as_float(u.w << 16); hi.w = __uint_as_float(u.w & 0xffff0000u);
            reinterpret_cast<float4*>(&nS[0][0])[p * 2 + 0] = lo;
            reinterpret_cast<float4*>(&nS[0][0])[p * 2 + 1] = hi;
        }
        __syncthreads();

        // init acc with Z (feat@W1 + biases), computed by phase A
        float4 acc[4];
        #pragma unroll
        for (int n = 0; n < 4; n++) {
            int v = base + slot * 4 + n;
            acc[n] = (v < n_nodes)
                ? __ldg(reinterpret_cast<const float4*>(g_z + (size_t)v * D) + og)
                : make_float4(0.f, 0.f, 0.f, 0.f);
        }

        #pragma unroll 4
        for (int k4 = 0; k4 < 16; k4++) {
            float na[4][4];
            #pragma unroll
            for (int n = 0; n < 4; n++) {
                float4 nv = reinterpret_cast<const float4*>(&nS[slot * 4 + n][0])[k4];
                na[n][0] = nv.x; na[n][1] = nv.y; na[n][2] = nv.z; na[n][3] = nv.w;
            }
            #pragma unroll
            for (int kk = 0; kk < 4; kk++) {
                int k = k4 * 4 + kk;
                float4 w2 = reinterpret_cast<const float4*>(W2t + k * D)[og];
                #pragma unroll
                for (int n = 0; n < 4; n++) {
                    acc[n].x += na[n][kk] * w2.x;
                    acc[n].y += na[n][kk] * w2.y;
                    acc[n].z += na[n][kk] * w2.z;
                    acc[n].w += na[n][kk] * w2.w;
                }
            }
        }

        #pragma unroll
        for (int n = 0; n < 4; n++) {
            if (base + slot * 4 + n < n_nodes) {
                gsum.x += fmaxf(acc[n].x, 0.f);
                gsum.y += fmaxf(acc[n].y, 0.f);
                gsum.z += fmaxf(acc[n].z, 0.f);
                gsum.w += fmaxf(acc[n].w, 0.f);
            }
        }
    }

    __syncthreads();
    reinterpret_cast<float4*>(&redbuf[slot][0])[og] = gsum;
    __syncthreads();
    if (t < D) {
        float s = 0.f;
        #pragma unroll
        for (int r = 0; r < 16; r++) s += redbuf[r][t];
        atomicAdd(out + t, s);
    }
}

// ---------------------------------------------------------------------------
// launch — inputs (metadata order): feat, emb, W1, b1, W2, b2, edge_src, edge_dst
// ---------------------------------------------------------------------------
extern "C" void kernel_launch(void* const* d_in, const int* in_sizes, int n_in,
                              void* d_out, int out_size) {
    (void)n_in; (void)out_size;
    const float* feat = (const float*)d_in[0];
    const float* emb  = (const float*)d_in[1];
    const float* W1   = (const float*)d_in[2];
    const float* b1   = (const float*)d_in[3];
    const float* W2   = (const float*)d_in[4];
    const float* b2   = (const float*)d_in[5];
    const int* esrc   = (const int*)d_in[6];
    const int* edst   = (const int*)d_in[7];
    float* out        = (float*)d_out;

    const int n_nodes = in_sizes[0] / D;
    const int n_edges = in_sizes[6];

    // 1) prep: emb->bf16, zero scratch + out
    {
        int n_grp = n_nodes * (D / 4);
        int blocks = (n_grp + 255) / 256;
        prep_kernel<<<blocks, 256>>>(emb, out, n_grp);
    }
    // 2) fused: scatter (L2-bound) + phase-A GEMM (FMA-bound), overlapped
    {
        int n_items = n_edges * 8;
        fused_kernel<<<NG + SCAT_BLK, 256>>>(feat, W1, b1, b2, esrc, edst,
                                             n_items, n_nodes);
    }
    // 3) phase-B: nbr@W2 + Z, relu, graph reduce
    mlpb_kernel<<<MLPB_BLOCKS, 256>>>(W2, out, n_nodes);
}